// round 14
// baseline (speedup 1.0000x reference)
#include <cuda_runtime.h>

// HartleyCosineConv2d: y[n,c,h,w] = a0*x[h] + a1*(x[rf(h-1)]+x[rf(h+1)])
//                                 + a2*(x[rf(h-2)]+x[rf(h+2)]) + a3*(x[rf(h-3)]+x[rf(h+3)])
// reflect boundary: rf(i) = -i for i<0, rf(i) = 2H-2-i for i>=H.
//
// FINAL champion — fixed point, confirmed across 6 identical submissions
// (174.53-174.82us wall, 161.0-162.5us kernel, 79.6-80.4% DRAM):
//  - register sliding window along H: exactly 1 load + 1 store per element
//    (compulsory-minimal traffic: 537MB r + 537MB w per call)
//  - float4 vectorization along W (LDG.128/STG.128, fully coalesced)
//  - unroll h by 8: 8 independent loads in flight per warp
//  - 128-thread blocks, 2 planes each, grid 1024: 64 regs -> 7 blocks/SM,
//    single wave (1024 <= 7*148), near-perfect SM balance
//  - DEFAULT cache ops: evict hints, write-through, L2 persist splits all
//    measured neutral-to-negative (R3/R5/R9); unroll-16, wider tiles, and
//    H-split ruled out (occupancy cliff R7 / halo traffic).
// ~6.35 TB/s = ~80% DRAM is the mixed 1:1 r/w HBM3e ceiling on sm_103a
// (bank turnaround; pure-read streams don't pay it). Issue=21%, L2=37%,
// ALU=5%, pipes idle: nothing else binds. Bytes cannot shrink (fp32
// in/out contract, zero cross-plane reuse).

constexpr int H = 256;
constexpr int W = 256;
constexpr int C = 256;
constexpr int W4 = W / 4;            // 64 float4 per row
constexpr int PLANES_PER_BLOCK = 2;  // 128 threads / 64 lanes

__device__ __forceinline__ float4 f4add(float4 a, float4 b) {
    return make_float4(a.x + b.x, a.y + b.y, a.z + b.z, a.w + b.w);
}

// r = a0*v3 + a1*(v2+v4) + a2*(v1+v5) + a3*(v0+n)
__device__ __forceinline__ float4 tap7(float a0, float a1, float a2, float a3,
                                       float4 v0, float4 v1, float4 v2,
                                       float4 v3, float4 v4, float4 v5,
                                       float4 n) {
    float4 s1 = f4add(v2, v4);
    float4 s2 = f4add(v1, v5);
    float4 s3 = f4add(v0, n);
    float4 r;
    r.x = fmaf(a0, v3.x, fmaf(a1, s1.x, fmaf(a2, s2.x, a3 * s3.x)));
    r.y = fmaf(a0, v3.y, fmaf(a1, s1.y, fmaf(a2, s2.y, a3 * s3.y)));
    r.z = fmaf(a0, v3.z, fmaf(a1, s1.z, fmaf(a2, s2.z, a3 * s3.z)));
    r.w = fmaf(a0, v3.w, fmaf(a1, s1.w, fmaf(a2, s2.w, a3 * s3.w)));
    return r;
}

__global__ __launch_bounds__(128)
void hartley_conv_kernel(const float4* __restrict__ x,
                         const float*  __restrict__ alpha,
                         float4*       __restrict__ y) {
    const int lane  = threadIdx.x & (W4 - 1);               // float4 col in row
    const int sub   = threadIdx.x >> 6;                     // plane within block
    const int plane = blockIdx.x * PLANES_PER_BLOCK + sub;  // n*C + c
    const int c     = plane & (C - 1);

    const size_t base = (size_t)plane * (H * W4) + lane;
    const float4* __restrict__ xp = x + base;
    float4*       __restrict__ yp = y + base;

    const float a0 = alpha[c * 4 + 0];
    const float a1 = alpha[c * 4 + 1];
    const float a2 = alpha[c * 4 + 2];
    const float a3 = alpha[c * 4 + 3];

    // Window v0..v5 = rows rf(h-3 .. h+2); new tap n = row rf(h+3).
    // Prefill for h=0: rf(-3..2) = 3,2,1,0,1,2 -> 4 distinct loads, reuse regs.
    float4 r3 = xp[3 * W4];
    float4 r2 = xp[2 * W4];
    float4 r1 = xp[1 * W4];
    float4 r0 = xp[0];
    float4 v0 = r3, v1 = r2, v2 = r1, v3 = r0, v4 = r1, v5 = r2;

    for (int h0 = 0; h0 < H; h0 += 8) {
        // rf(i) for i in [3, H+3): only upper reflection -> min(i, 2H-2-i)
        float4 nb[8];
        #pragma unroll
        for (int j = 0; j < 8; j++) {
            const int i = min(h0 + 3 + j, 2 * H - 2 - (h0 + 3 + j));
            nb[j] = xp[i * W4];          // 8 independent LDG.128 in flight
        }

        float4 ob[8];
        #pragma unroll
        for (int j = 0; j < 8; j++) {
            ob[j] = tap7(a0, a1, a2, a3, v0, v1, v2, v3, v4, v5, nb[j]);
            v0 = v1; v1 = v2; v2 = v3; v3 = v4; v4 = v5; v5 = nb[j];
        }

        #pragma unroll
        for (int j = 0; j < 8; j++)
            yp[(h0 + j) * W4] = ob[j];
    }
}

extern "C" void kernel_launch(void* const* d_in, const int* in_sizes, int n_in,
                              void* d_out, int out_size) {
    const float* x     = (const float*)d_in[0];
    const float* alpha = (const float*)d_in[1];
    float*       yout  = (float*)d_out;

    const int planes = in_sizes[0] / (H * W);       // N*C = 2048
    const int grid   = planes / PLANES_PER_BLOCK;   // 1024

    hartley_conv_kernel<<<grid, 128>>>((const float4*)x, alpha, (float4*)yout);
}

// round 15
// speedup vs baseline: 1.0536x; 1.0536x over previous
#include <cuda_runtime.h>

// HartleyCosineConv2d: y[n,c,h,w] = a0*x[h] + a1*(x[rf(h-1)]+x[rf(h+1)])
//                                 + a2*(x[rf(h-2)]+x[rf(h+2)]) + a3*(x[rf(h-3)]+x[rf(h+3)])
// reflect boundary: rf(i) = -i for i<0, rf(i) = 2H-2-i for i>=H.
//
// R15: last untested scheduling cell — 64-thread blocks, 1 plane/block,
// grid 2048. Identical per-warp code and traffic to the champion; finer
// CTA granularity halves the straggler-block drain quantum and improves
// end-of-kernel packing (R14 exposed ±2% per-SM run variance). 64 regs x
// 64 thr -> 14+ blocks/SM resident, single wave, ~28 warps/SM (same as
// champion). All other knobs at their measured optima: register sliding
// window (1 ld + 1 st / element), float4, unroll 8, default cache ops.

constexpr int H = 256;
constexpr int W = 256;
constexpr int C = 256;
constexpr int W4 = W / 4;            // 64 float4 per row

__device__ __forceinline__ float4 f4add(float4 a, float4 b) {
    return make_float4(a.x + b.x, a.y + b.y, a.z + b.z, a.w + b.w);
}

// r = a0*v3 + a1*(v2+v4) + a2*(v1+v5) + a3*(v0+n)
__device__ __forceinline__ float4 tap7(float a0, float a1, float a2, float a3,
                                       float4 v0, float4 v1, float4 v2,
                                       float4 v3, float4 v4, float4 v5,
                                       float4 n) {
    float4 s1 = f4add(v2, v4);
    float4 s2 = f4add(v1, v5);
    float4 s3 = f4add(v0, n);
    float4 r;
    r.x = fmaf(a0, v3.x, fmaf(a1, s1.x, fmaf(a2, s2.x, a3 * s3.x)));
    r.y = fmaf(a0, v3.y, fmaf(a1, s1.y, fmaf(a2, s2.y, a3 * s3.y)));
    r.z = fmaf(a0, v3.z, fmaf(a1, s1.z, fmaf(a2, s2.z, a3 * s3.z)));
    r.w = fmaf(a0, v3.w, fmaf(a1, s1.w, fmaf(a2, s2.w, a3 * s3.w)));
    return r;
}

__global__ __launch_bounds__(64)
void hartley_conv_kernel(const float4* __restrict__ x,
                         const float*  __restrict__ alpha,
                         float4*       __restrict__ y) {
    const int lane  = threadIdx.x;            // float4 column in row (0..63)
    const int plane = blockIdx.x;             // n*C + c
    const int c     = plane & (C - 1);

    const size_t base = (size_t)plane * (H * W4) + lane;
    const float4* __restrict__ xp = x + base;
    float4*       __restrict__ yp = y + base;

    const float a0 = alpha[c * 4 + 0];
    const float a1 = alpha[c * 4 + 1];
    const float a2 = alpha[c * 4 + 2];
    const float a3 = alpha[c * 4 + 3];

    // Window v0..v5 = rows rf(h-3 .. h+2); new tap n = row rf(h+3).
    // Prefill for h=0: rf(-3..2) = 3,2,1,0,1,2 -> 4 distinct loads, reuse regs.
    float4 r3 = xp[3 * W4];
    float4 r2 = xp[2 * W4];
    float4 r1 = xp[1 * W4];
    float4 r0 = xp[0];
    float4 v0 = r3, v1 = r2, v2 = r1, v3 = r0, v4 = r1, v5 = r2;

    for (int h0 = 0; h0 < H; h0 += 8) {
        // rf(i) for i in [3, H+3): only upper reflection -> min(i, 2H-2-i)
        float4 nb[8];
        #pragma unroll
        for (int j = 0; j < 8; j++) {
            const int i = min(h0 + 3 + j, 2 * H - 2 - (h0 + 3 + j));
            nb[j] = xp[i * W4];          // 8 independent LDG.128 in flight
        }

        float4 ob[8];
        #pragma unroll
        for (int j = 0; j < 8; j++) {
            ob[j] = tap7(a0, a1, a2, a3, v0, v1, v2, v3, v4, v5, nb[j]);
            v0 = v1; v1 = v2; v2 = v3; v3 = v4; v4 = v5; v5 = nb[j];
        }

        #pragma unroll
        for (int j = 0; j < 8; j++)
            yp[(h0 + j) * W4] = ob[j];
    }
}

extern "C" void kernel_launch(void* const* d_in, const int* in_sizes, int n_in,
                              void* d_out, int out_size) {
    const float* x     = (const float*)d_in[0];
    const float* alpha = (const float*)d_in[1];
    float*       yout  = (float*)d_out;

    const int planes = in_sizes[0] / (H * W);   // N*C = 2048
    hartley_conv_kernel<<<planes, 64>>>((const float4*)x, alpha, (float4*)yout);
}